// round 15
// baseline (speedup 1.0000x reference)
#include <cuda_runtime.h>
#include <cuda_fp16.h>
#include <cstdint>
#include <math.h>

#define N_NODES 10000
#define F_DIM   128
#define H_DIM   64
#define C_DIM   2
#define G_CNT   4
#define E_EDGES 320000
#define NPAD    10112                  // 79 * 128

// ---------------- scratch (device globals; no dynamic alloc) ----------------
__device__ float  g_kf[F_DIM];
__device__ float  g_ex[(size_t)NPAD * F_DIM];
__device__ __align__(16) __half g_exs[2][(size_t)NPAD * F_DIM];  // fp16 hi/lo splits
__device__ float  g_colinv[NPAD];
__device__ float2 g_W1p[G_CNT * F_DIM * 32];               // packed (c, c+32) pairs
__device__ float2 g_h1p[(size_t)G_CNT * N_NODES * 32];     // packed h1
__device__ float  g_al4[G_CNT * N_NODES], g_ar4[G_CNT * N_NODES];
__device__ float  g_al2a[G_CNT * N_NODES], g_ar2a[G_CNT * N_NODES];
__device__ float2 g_h2a[G_CNT * N_NODES];
__device__ float  g_oacc[G_CNT][N_NODES];
__device__ int    g_cnt[2][NPAD];
__device__ int    g_off[2][NPAD];
__device__ int    g_cur[2][NPAD];
__device__ int    g_csr[2][E_EDGES];
__device__ float  g_w2[NPAD];            // 2p-1 (zero padded)
__device__ double g_t[N_NODES];          // row accumulators for norm
__device__ float  g_loss[1];
__device__ float  g_masksum[1];

// ---------------- helpers ----------------
__device__ __forceinline__ float wredsum(float v) {
    #pragma unroll
    for (int o = 16; o > 0; o >>= 1) v += __shfl_xor_sync(0xffffffffu, v, o);
    return v;
}
__device__ __forceinline__ float sigmoidf_(float x) { return 1.0f / (1.0f + expf(-x)); }
__device__ __forceinline__ uint32_t smem_to_u32(const void* smem_ptr) {
    uint32_t addr;
    asm("{ .reg .u64 tmp; cvta.to.shared.u64 tmp, %1; cvt.u32.u64 %0, tmp; }"
        : "=r"(addr) : "l"(smem_ptr));
    return addr;
}

#define LDMATRIX_X4(r0, r1, r2, r3, addr) \
    asm volatile("ldmatrix.sync.aligned.m8n8.x4.shared.b16 {%0,%1,%2,%3}, [%4];" \
        : "=r"(r0), "=r"(r1), "=r"(r2), "=r"(r3) : "r"(addr))
#define LDMATRIX_X2(r0, r1, addr) \
    asm volatile("ldmatrix.sync.aligned.m8n8.x2.shared.b16 {%0,%1}, [%2];" \
        : "=r"(r0), "=r"(r1) : "r"(addr))
#define MMA16816F16(d, a, b) \
    asm volatile("mma.sync.aligned.m16n8k16.row.col.f32.f16.f16.f32 " \
        "{%0,%1,%2,%3}, {%4,%5,%6,%7}, {%8,%9}, {%0,%1,%2,%3};" \
        : "+f"((d)[0]), "+f"((d)[1]), "+f"((d)[2]), "+f"((d)[3]) \
        : "r"((a)[0]), "r"((a)[1]), "r"((a)[2]), "r"((a)[3]), "r"((b)[0]), "r"((b)[1]))

// ---------------- k_init ----------------
__global__ void k_init(const float* __restrict__ logit_p,
                       const float* __restrict__ emb_w,
                       float* __restrict__ pw_out) {
    int f = threadIdx.x;
    if (f < F_DIM) {
        float p = sigmoidf_(logit_p[f]);
        pw_out[f] = 1.0f - p;
        const float EPSf = 2.2204460492503131e-16f;
        float approx = logf(p + EPSf) - logf(1.0f - p + EPSf);
        float keep = 1.0f - sigmoidf_(approx * 10.0f);
        g_kf[f] = keep * sigmoidf_(emb_w[f]);
        if (f == 0) { g_loss[0] = 0.0f; g_masksum[0] = 0.0f; }
    }
}

// ---------------- k_prep: pack W1 ----------------
__global__ void k_prep(const float* __restrict__ W1) {
    int idx = blockIdx.x * 256 + threadIdx.x;
    if (idx >= G_CNT * F_DIM * 32) return;
    int lane = idx & 31;
    int k = (idx >> 5) & 127;
    int g = idx >> 12;
    const float* Wg = W1 + g * F_DIM * H_DIM + k * H_DIM;
    g_W1p[idx] = make_float2(Wg[lane], Wg[lane + 32]);
}

// ---------------- k_ex: ex = x*kf (exact), fp16x2 split fused, masksum ----------------
__global__ void k_ex(const float* __restrict__ x, const int* __restrict__ mask) {
    int w = blockIdx.x * 8 + (threadIdx.x >> 5);
    if (w >= NPAD) return;
    int lane = threadIdx.x & 31;
    size_t base = (size_t)w * F_DIM + lane * 4;
    float4 e = make_float4(0.f, 0.f, 0.f, 0.f);
    if (w < N_NODES) {
        float4 kf = *(const float4*)&g_kf[lane * 4];
        float4 xv = *(const float4*)&x[base];
        e.x = __fmul_rn(xv.x, kf.x); e.y = __fmul_rn(xv.y, kf.y);
        e.z = __fmul_rn(xv.z, kf.z); e.w = __fmul_rn(xv.w, kf.w);
        if (lane == 0 && mask[w] > 0) atomicAdd(&g_masksum[0], 1.0f);
    }
    *(float4*)&g_ex[base] = e;
    const float* ep = (const float*)&e;
    __half hs[4], ms[4];
    #pragma unroll
    for (int q = 0; q < 4; q++) {
        float v = ep[q];
        __half h = __float2half_rn(v);
        float r = v - __half2float(h);
        hs[q] = h;
        ms[q] = __float2half_rn(r);
    }
    *(uint2*)&g_exs[0][base] = *(uint2*)hs;
    *(uint2*)&g_exs[1][base] = *(uint2*)ms;
    if (lane == 1) { g_cnt[0][w] = 0; g_cnt[1][w] = 0; }
}

// ---------------- k_colinv: SACRED — matched reference emitter order; do not touch ----------------
__global__ void k_colinv(const float* __restrict__ x) {
    int w = blockIdx.x * 8 + (threadIdx.x >> 5);
    if (w >= NPAD) return;
    int lane = threadIdx.x & 31;
    if (w < N_NODES) {
        const float* xr = x + (size_t)w * F_DIM;
        float2 xa = *(const float2*)&xr[2 * lane];
        float2 xb = *(const float2*)&xr[2 * lane + 64];
        float2 ka = *(const float2*)&g_kf[2 * lane];
        float2 kb = *(const float2*)&g_kf[2 * lane + 64];
        float i0 = __fadd_rn(__fmul_rn(xa.x, ka.x), __fmul_rn(xa.y, ka.y));
        float i1 = __fadd_rn(__fmul_rn(xb.x, kb.x), __fmul_rn(xb.y, kb.y));
        float s = __fadd_rn(i0, i1);
        s = wredsum(s);
        if (lane == 0) g_colinv[w] = __fdiv_rn(1.0f, __fadd_rn(s, 1e-6f));
    } else if (lane == 0) {
        g_colinv[w] = 0.0f;
    }
}

// ---------------- CSR build ----------------
__global__ void k_csr_hist(const int* __restrict__ e0, const int* __restrict__ e1) {
    int idx = blockIdx.x * 256 + threadIdx.x;
    if (idx >= E_EDGES) return;
    const int* ei = blockIdx.y ? e1 : e0;
    atomicAdd(&g_cnt[blockIdx.y][ei[E_EDGES + idx]], 1);
}

__global__ void k_csr_scan() {
    __shared__ int part[1024];
    int t = threadIdx.x;
    for (int list = 0; list < 2; list++) {
        const int chunk = 10;
        int base = t * chunk;
        int sum = 0;
        #pragma unroll
        for (int i = 0; i < chunk; i++) {
            int idx = base + i;
            if (idx < N_NODES) sum += g_cnt[list][idx];
        }
        part[t] = sum;
        __syncthreads();
        for (int off = 1; off < 1024; off <<= 1) {
            int u = (t >= off) ? part[t - off] : 0;
            __syncthreads();
            part[t] += u;
            __syncthreads();
        }
        int run = part[t] - sum;
        for (int i = 0; i < chunk; i++) {
            int idx = base + i;
            if (idx < N_NODES) {
                g_off[list][idx] = run;
                g_cur[list][idx] = run;
                run += g_cnt[list][idx];
            }
        }
        __syncthreads();
    }
}

__global__ void k_csr_scatter(const int* __restrict__ e0, const int* __restrict__ e1) {
    int idx = blockIdx.x * 256 + threadIdx.x;
    if (idx >= E_EDGES) return;
    int list = blockIdx.y;
    const int* ei = list ? e1 : e0;
    int s = ei[idx], d = ei[E_EDGES + idx];
    int pos = atomicAdd(&g_cur[list][d], 1);
    g_csr[list][pos] = s;
}

// ---------------- k_h1_all ----------------
__global__ __launch_bounds__(256) void k_h1_all(const float* __restrict__ x,
                                                const float* __restrict__ as1,
                                                const float* __restrict__ ad1) {
    int warp = blockIdx.x * 8 + (threadIdx.x >> 5);
    int lane = threadIdx.x & 31;
    if (warp >= 2500) return;
    int n0 = warp * 4;

    unsigned long long acc[4][4];
    #pragma unroll
    for (int g = 0; g < 4; g++)
        #pragma unroll
        for (int nd = 0; nd < 4; nd++) acc[g][nd] = 0ull;

    const float* xr = x + (size_t)n0 * F_DIM;
    for (int k = 0; k < F_DIM; k++) {
        unsigned long long xd[4];
        #pragma unroll
        for (int nd = 0; nd < 4; nd++) {
            unsigned xu = __float_as_uint(__ldg(xr + nd * F_DIM + k));
            asm("mov.b64 %0, {%1, %1};" : "=l"(xd[nd]) : "r"(xu));
        }
        #pragma unroll
        for (int g = 0; g < 4; g++) {
            float2 wv = g_W1p[(g * F_DIM + k) * 32 + lane];
            unsigned long long wd = *reinterpret_cast<unsigned long long*>(&wv);
            #pragma unroll
            for (int nd = 0; nd < 4; nd++)
                asm("fma.rn.f32x2 %0, %1, %2, %0;"
                    : "+l"(acc[g][nd]) : "l"(xd[nd]), "l"(wd));
        }
    }
    #pragma unroll
    for (int g = 0; g < 4; g++) {
        float asl = as1[g * 64 + lane], ash = as1[g * 64 + lane + 32];
        float adl = ad1[g * 64 + lane], adh = ad1[g * 64 + lane + 32];
        #pragma unroll
        for (int nd = 0; nd < 4; nd++) {
            unsigned long long v = acc[g][nd];
            float lo = __uint_as_float((unsigned)(v & 0xffffffffull));
            float hi = __uint_as_float((unsigned)(v >> 32));
            g_h1p[((size_t)g * N_NODES + n0 + nd) * 32 + lane] = make_float2(lo, hi);
            float ap = wredsum(lo * asl + hi * ash);
            float rp = wredsum(lo * adl + hi * adh);
            if (lane == 0) {
                g_al4[g * N_NODES + n0 + nd] = ap;
                g_ar4[g * N_NODES + n0 + nd] = rp;
            }
        }
    }
}

// ---------------- k_gat1_all ----------------
__global__ void k_gat1_all(const float* __restrict__ b1, const float* __restrict__ gm,
                           const float* __restrict__ bt, const float* __restrict__ W2,
                           const float* __restrict__ as2, const float* __restrict__ ad2) {
    int g = blockIdx.y, list = g & 1;
    int d = blockIdx.x * 8 + (threadIdx.x >> 5);
    if (d >= N_NODES) return;
    int lane = threadIdx.x & 31;

    const float* al = g_al4 + g * N_NODES;
    float ard = g_ar4[g * N_NODES + d];
    const float2* h1p = g_h1p + (size_t)g * N_NODES * 32;

    float a0 = al[d] + ard; a0 = (a0 >= 0.f) ? a0 : 0.2f * a0;
    float ee = expf(a0);
    float2 hd = h1p[d * 32 + lane];
    float accx = ee * hd.x, accy = ee * hd.y, s = ee;

    int k1 = g_off[list][d] + g_cnt[list][d];
    for (int k = g_off[list][d]; k < k1; k++) {
        int src = g_csr[list][k];
        float a = al[src] + ard; a = (a >= 0.f) ? a : 0.2f * a;
        float e = expf(a);
        float2 h = h1p[src * 32 + lane];
        s += e;
        accx = fmaf(e, h.x, accx);
        accy = fmaf(e, h.y, accy);
    }
    float inv = 1.0f / (s + 1e-16f);
    float h0  = accx * inv + b1[g * 64 + lane];
    float h1v = accy * inv + b1[g * 64 + lane + 32];
    const float BNS = 0.9999950000374997f;
    h0  = h0  * gm[g * 64 + lane]      * BNS + bt[g * 64 + lane];
    h1v = h1v * gm[g * 64 + lane + 32] * BNS + bt[g * 64 + lane + 32];
    h0  = (h0  >= 0.f) ? h0  : 0.01f * h0;
    h1v = (h1v >= 0.f) ? h1v : 0.01f * h1v;
    const float* W2g = W2 + g * H_DIM * C_DIM;
    float p0 = wredsum(h0 * W2g[lane * 2]     + h1v * W2g[(lane + 32) * 2]);
    float p1 = wredsum(h0 * W2g[lane * 2 + 1] + h1v * W2g[(lane + 32) * 2 + 1]);
    if (lane == 0) {
        g_h2a[g * N_NODES + d] = make_float2(p0, p1);
        g_al2a[g * N_NODES + d] = p0 * as2[g * 2] + p1 * as2[g * 2 + 1];
        g_ar2a[g * N_NODES + d] = p0 * ad2[g * 2] + p1 * ad2[g * 2 + 1];
    }
}

// ---------------- k_gat2_all ----------------
__global__ void k_gat2_all(const float* __restrict__ b2, const int* __restrict__ y,
                           const int* __restrict__ mask) {
    int g = blockIdx.y, list = g & 1;
    int d = blockIdx.x * 8 + (threadIdx.x >> 5);
    if (d >= N_NODES) return;
    int lane = threadIdx.x & 31;

    const float* al2 = g_al2a + g * N_NODES;
    float ar2d = g_ar2a[g * N_NODES + d];
    const float2* h2 = g_h2a + g * N_NODES;

    float s = 0.f, o0 = 0.f, o1 = 0.f;
    int k0 = g_off[list][d], k1 = k0 + g_cnt[list][d];
    for (int k = k0 + lane; k < k1; k += 32) {
        int src = g_csr[list][k];
        float a = al2[src] + ar2d; a = (a >= 0.f) ? a : 0.2f * a;
        float e = expf(a);
        float2 h = h2[src];
        s += e;
        o0 = fmaf(e, h.x, o0);
        o1 = fmaf(e, h.y, o1);
    }
    s = wredsum(s); o0 = wredsum(o0); o1 = wredsum(o1);
    if (lane == 0) {
        float a = al2[d] + ar2d; a = (a >= 0.f) ? a : 0.2f * a;
        float es = expf(a);
        float2 hd = h2[d];
        s += es; o0 += es * hd.x; o1 += es * hd.y;
        float inv = 1.0f / (s + 1e-16f);
        float v0 = o0 * inv + b2[g * 2];
        float v1 = o1 * inv + b2[g * 2 + 1];
        float mx = fmaxf(v0, v1);
        float lse = mx + logf(expf(v0 - mx) + expf(v1 - mx));
        float lp0 = v0 - lse, lp1 = v1 - lse;
        g_oacc[g][d] = expf(lp1);
        if (mask[d] > 0) atomicAdd(&g_loss[0], (y[d] == 0) ? lp0 : lp1);
    }
}

// ---------------- k_nodep ----------------
__global__ void k_nodep(float* __restrict__ dout) {
    int i = blockIdx.x * blockDim.x + threadIdx.x;
    if (i < NPAD) {
        if (i < N_NODES) {
            float p = (((g_oacc[0][i] + g_oacc[1][i]) + g_oacc[2][i]) + g_oacc[3][i]) * 0.25f;
            dout[i] = p;
            g_w2[i] = 2.0f * p - 1.0f;
            g_t[i] = 0.0;
        } else {
            g_w2[i] = 0.0f;
        }
    }
    if (i == 0) dout[N_NODES] = -g_loss[0] / (g_masksum[0] * (float)G_CNT);
}

// ---------------- k_graph_mma: fp16x2 GEMM, 128x64 tiles, 2 CTA/SM, fused t ----------------
// Tiles: bi in 128Z, bj in 64Z, bj >= bi. Transposed emission iff bj >= bi+128.
// smem: [A_h][A_m] 128x272 each, [B_h][B_m] 64x272 each; epilogue reuses as Cst[128][69].
#define TSTRIDE   272
#define TILE_A    (128 * TSTRIDE)          // 34816
#define TILE_Bb   (64 * TSTRIDE)           // 17408
#define SMEM_MMA  (1024 + 2 * TILE_A + 2 * TILE_Bb)   // 105472

__global__ __launch_bounds__(512, 2) void k_graph_mma(float* __restrict__ out) {
    extern __shared__ char smem[];
    int bib = blockIdx.y;            // 0..78  (M panel, 128 rows)
    int bjb = blockIdx.x;            // 0..157 (N panel, 64 cols)
    if (bjb < 2 * bib) return;
    int bi = bib * 128, bj = bjb * 64;
    int tid = threadIdx.x;
    int wid = tid >> 5, lane = tid & 31;
    uint32_t tbase = smem_to_u32(smem) + 1024;

    // Fill A splits (128 rows each)
    #pragma unroll
    for (int s = 0; s < 2; s++) {
        char* dst = smem + 1024 + s * TILE_A;
        const __half* src = g_exs[s] + (size_t)bi * F_DIM;
        #pragma unroll
        for (int it = 0; it < 4; it++) {
            int t = it * 512 + tid;            // 0..2047
            int row = t >> 4, ch = t & 15;
            uint4 v = *(const uint4*)&src[(size_t)row * F_DIM + ch * 8];
            *(uint4*)(dst + row * TSTRIDE + ch * 16) = v;
        }
    }
    // Fill B splits (64 rows each)
    #pragma unroll
    for (int s = 0; s < 2; s++) {
        char* dst = smem + 1024 + 2 * TILE_A + s * TILE_Bb;
        const __half* src = g_exs[s] + (size_t)bj * F_DIM;
        #pragma unroll
        for (int it = 0; it < 2; it++) {
            int t = it * 512 + tid;            // 0..1023
            int row = t >> 4, ch = t & 15;
            uint4 v = *(const uint4*)&src[(size_t)row * F_DIM + ch * 8];
            *(uint4*)(dst + row * TSTRIDE + ch * 16) = v;
        }
    }
    __syncthreads();

    // Warp layout: 4 (M) x 4 (N); warp tile 32x16
    int mw = wid & 3, nw = wid >> 2;
    float acc[2][2][4];
    #pragma unroll
    for (int mf = 0; mf < 2; mf++)
        #pragma unroll
        for (int nf = 0; nf < 2; nf++)
            #pragma unroll
            for (int r = 0; r < 4; r++) acc[mf][nf][r] = 0.f;

    int rowA = mw * 32 + (lane & 15);
    int kselA = ((lane >> 4) << 3);
    int rowB = nw * 16 + (lane & 7);
    int kselB = (lane & 8);

    #pragma unroll 1
    for (int ks = 0; ks < 8; ks++) {
        int kb = ks * 16;
        uint32_t ah[2][4], am[2][4];
        uint32_t ah_base = tbase + (kb + kselA) * 2;
        uint32_t am_base = ah_base + TILE_A;
        #pragma unroll
        for (int mf = 0; mf < 2; mf++) {
            uint32_t ro = (rowA + mf * 16) * TSTRIDE;
            LDMATRIX_X4(ah[mf][0], ah[mf][1], ah[mf][2], ah[mf][3], ah_base + ro);
            LDMATRIX_X4(am[mf][0], am[mf][1], am[mf][2], am[mf][3], am_base + ro);
        }
        uint32_t bh[2][2], bm[2][2];
        uint32_t bh_base = tbase + 2 * TILE_A + (kb + kselB) * 2;
        uint32_t bm_base = bh_base + TILE_Bb;
        #pragma unroll
        for (int nf = 0; nf < 2; nf++) {
            uint32_t ro = (rowB + nf * 8) * TSTRIDE;
            LDMATRIX_X2(bh[nf][0], bh[nf][1], bh_base + ro);
            LDMATRIX_X2(bm[nf][0], bm[nf][1], bm_base + ro);
        }
        #pragma unroll
        for (int mf = 0; mf < 2; mf++)
            #pragma unroll
            for (int nf = 0; nf < 2; nf++) {
                MMA16816F16(acc[mf][nf], ah[mf], bh[nf]);
                MMA16816F16(acc[mf][nf], ah[mf], bm[nf]);
                MMA16816F16(acc[mf][nf], am[mf], bh[nf]);
            }
    }
    __syncthreads();   // done reading tiles; reuse smem as Cst

    float* Cst = (float*)(smem + 1024);    // [128][69]
    {
        int qr = lane >> 2;
        int qc = (lane & 3) * 2;
        #pragma unroll
        for (int mf = 0; mf < 2; mf++) {
            int m = mw * 32 + mf * 16 + qr;
            #pragma unroll
            for (int nf = 0; nf < 2; nf++) {
                int n = nw * 16 + nf * 8 + qc;
                Cst[m * 69 + n]           = acc[mf][nf][0];
                Cst[m * 69 + n + 1]       = acc[mf][nf][1];
                Cst[(m + 8) * 69 + n]     = acc[mf][nf][2];
                Cst[(m + 8) * 69 + n + 1] = acc[mf][nf][3];
            }
        }
    }
    __syncthreads();

    // Direct emission: out[bi+m][bj+n] (n = lane + 32*nb, nb<2)
    {
        int cj0 = bj + lane, cj1 = bj + 32 + lane;
        float cv0 = g_colinv[cj0], cv1 = g_colinv[cj1];
        float wv0 = g_w2[cj0],     wv1 = g_w2[cj1];
        #pragma unroll 1
        for (int k = 0; k < 8; k++) {
            int m = wid * 8 + k;
            int r = bi + m;
            if (r >= N_NODES) continue;
            size_t rowb = (size_t)r * N_NODES;
            float v0 = __fmul_rn(Cst[m * 69 + lane], cv0);
            float v1 = __fmul_rn(Cst[m * 69 + 32 + lane], cv1);
            if (cj0 < N_NODES) out[rowb + cj0] = v0;
            if (cj1 < N_NODES) out[rowb + cj1] = v1;
            float acc2 = wredsum(fmaf(v1, wv1, v0 * wv0));
            if (lane == 0) atomicAdd(&g_t[r], (double)acc2);
        }
    }

    // Transposed emission iff fully off-diagonal panel: bj >= bi + 128
    if (bj >= bi + 128) {
        float civ[4], wv[4];
        #pragma unroll
        for (int mb = 0; mb < 4; mb++) {
            int ri = bi + mb * 32 + lane;
            civ[mb] = g_colinv[ri];
            wv[mb] = g_w2[ri];
        }
        #pragma unroll 1
        for (int k = 0; k < 4; k++) {
            int n = wid * 4 + k;
            int cg = bj + n;
            if (cg >= N_NODES) continue;
            float acc2 = 0.f;
            size_t rowb = (size_t)cg * N_NODES;
            #pragma unroll
            for (int mb = 0; mb < 4; mb++) {
                int ri = bi + mb * 32 + lane;
                float val = __fmul_rn(Cst[(mb * 32 + lane) * 69 + n], civ[mb]);
                if (ri < N_NODES) out[rowb + ri] = val;
                acc2 = fmaf(val, wv[mb], acc2);
            }
            acc2 = wredsum(acc2);
            if (lane == 0) atomicAdd(&g_t[cg], (double)acc2);
        }
    }
}

// ---------------- k_normf ----------------
__global__ void k_normf(float* __restrict__ outp) {
    int i = blockIdx.x * blockDim.x + threadIdx.x;
    if (i >= N_NODES) return;
    float t = (float)g_t[i];
    outp[i] = 1.0f / (1.0f + expf(-t));
}

// ---------------- launch ----------------
extern "C" void kernel_launch(void* const* d_in, const int* in_sizes, int n_in,
                              void* d_out, int out_size) {
    const float* x      = (const float*)d_in[0];
    const int*   y      = (const int*)d_in[1];
    const int*   mask   = (const int*)d_in[2];
    const int*   e_ppi  = (const int*)d_in[3];
    const int*   e_hom  = (const int*)d_in[4];
    const float* W1     = (const float*)d_in[5];
    const float* as1    = (const float*)d_in[6];
    const float* ad1    = (const float*)d_in[7];
    const float* b1     = (const float*)d_in[8];
    const float* gamma_ = (const float*)d_in[9];
    const float* beta_  = (const float*)d_in[10];
    const float* W2     = (const float*)d_in[11];
    const float* as2    = (const float*)d_in[12];
    const float* ad2    = (const float*)d_in[13];
    const float* b2     = (const float*)d_in[14];
    const float* emb_w  = (const float*)d_in[15];
    const float* logitp = (const float*)d_in[16];
    float* out = (float*)d_out;

    const size_t OFF_NORM  = (size_t)N_NODES + 1;
    const size_t OFF_GRAPH = (size_t)2 * N_NODES + 1;
    const size_t OFF_PW    = OFF_GRAPH + (size_t)N_NODES * N_NODES;

    cudaFuncSetAttribute(k_graph_mma, cudaFuncAttributeMaxDynamicSharedMemorySize, SMEM_MMA);

    k_init<<<1, 128>>>(logitp, emb_w, out + OFF_PW);
    k_prep<<<(G_CNT * F_DIM * 32 + 255) / 256, 256>>>(W1);
    k_ex<<<NPAD / 8, 256>>>(x, mask);
    k_colinv<<<NPAD / 8, 256>>>(x);

    dim3 eg((E_EDGES + 255) / 256, 2);
    k_csr_hist<<<eg, 256>>>(e_ppi, e_hom);
    k_csr_scan<<<1, 1024>>>();
    k_csr_scatter<<<eg, 256>>>(e_ppi, e_hom);

    k_h1_all<<<313, 256>>>(x, as1, ad1);

    dim3 gg1(1250, G_CNT);
    k_gat1_all<<<gg1, 256>>>(b1, gamma_, beta_, W2, as2, ad2);
    k_gat2_all<<<gg1, 256>>>(b2, y, mask);

    k_nodep<<<(NPAD + 255) / 256, 256>>>(out);
    dim3 ggr(158, 79);
    k_graph_mma<<<ggr, 512, SMEM_MMA>>>(out + OFF_GRAPH);
    k_normf<<<(N_NODES + 255) / 256, 256>>>(out + OFF_NORM);
}